// round 1
// baseline (speedup 1.0000x reference)
#include <cuda_runtime.h>
#include <cstdint>
#include <math.h>

// ---------------- problem constants ----------------
#define NB    4
#define NH    6
#define NMAP  24          // NB*NH
#define SEQ   1024        // H*W
#define DH    64
#define CDIM  384
#define KTOP  734003      // int(0.7 * 1024 * 1024)
#define SCALEF 0.125f     // 64^-0.5

// output offsets (element counts, float32)
#define OP_OFF 0
#define AM_OFF 1572864
#define AC_OFF 1576960
#define AN_OFF 26742784
#define BM_OFF 51908608

// ---------------- scratch (device globals; no cudaMalloc allowed) ----------------
__device__ float g_q[NB * CDIM * SEQ];            // [b][o][n]  (o = h*64+d)
__device__ float g_k[NB * CDIM * SEQ];
__device__ float g_v[NB * CDIM * SEQ];
__device__ float g_o[NB * CDIM * SEQ];            // attn@v result, [b][o][n]
__device__ float g_attn[(size_t)NMAP * SEQ * SEQ];// softmax-ed attention [bh][n][m]
__device__ unsigned g_h1[NMAP * 65536];
__device__ unsigned g_h2[NMAP * 65536];
__device__ unsigned g_H[NMAP];
__device__ unsigned g_above[NMAP];
__device__ unsigned g_thr[NMAP];
__device__ int g_need[NMAP];
__device__ int g_ceq[NMAP];
__device__ int g_cut[NMAP];
__device__ float g_part[NMAP * 16 * SEQ];         // column-sum partials for attn_map

// ---------------- QKV projection: C[o,n] = sum_c W[o,c] * X[c,n] ----------------
// M=384, N=1024, K=384. 128x128 tile, 256 threads, 8x8 microtile, BK=16.
__global__ void __launch_bounds__(256)
proj_kernel(const float* __restrict__ qin, const float* __restrict__ cin,
            const float* __restrict__ Wq, const float* __restrict__ Wk,
            const float* __restrict__ Wv)
{
    int bz = blockIdx.z;
    int b = bz / 3, p = bz - b * 3;
    const float* X = (p == 0 ? qin : cin) + b * CDIM * SEQ;
    const float* W = (p == 0 ? Wq : (p == 1 ? Wk : Wv));
    float* Y = (p == 0 ? g_q : (p == 1 ? g_k : g_v)) + b * CDIM * SEQ;

    __shared__ float As[16][132];
    __shared__ float Bs[16][132];

    int tid = threadIdx.x;
    int o0 = blockIdx.y * 128, n0 = blockIdx.x * 128;
    int ty = tid >> 4, tx = tid & 15;

    float acc[8][8];
#pragma unroll
    for (int i = 0; i < 8; i++)
#pragma unroll
        for (int j = 0; j < 8; j++) acc[i][j] = 0.f;

    int arow = tid >> 2, acol = (tid & 3) << 2;
    int brow = tid >> 5, bcol = (tid & 31) << 2;

    for (int k0 = 0; k0 < CDIM; k0 += 16) {
#pragma unroll
        for (int r = 0; r < 2; r++) {
            float4 w4 = *(const float4*)&W[(o0 + arow + r * 64) * CDIM + k0 + acol];
            As[acol + 0][arow + r * 64] = w4.x;
            As[acol + 1][arow + r * 64] = w4.y;
            As[acol + 2][arow + r * 64] = w4.z;
            As[acol + 3][arow + r * 64] = w4.w;
        }
#pragma unroll
        for (int r = 0; r < 2; r++) {
            *(float4*)&Bs[brow + r * 8][bcol] =
                *(const float4*)&X[(k0 + brow + r * 8) * SEQ + n0 + bcol];
        }
        __syncthreads();
#pragma unroll
        for (int kk = 0; kk < 16; kk++) {
            float a[8], bb[8];
            *(float4*)(a)     = *(float4*)&As[kk][ty * 8];
            *(float4*)(a + 4) = *(float4*)&As[kk][ty * 8 + 4];
            *(float4*)(bb)     = *(float4*)&Bs[kk][tx * 8];
            *(float4*)(bb + 4) = *(float4*)&Bs[kk][tx * 8 + 4];
#pragma unroll
            for (int i = 0; i < 8; i++)
#pragma unroll
                for (int j = 0; j < 8; j++) acc[i][j] += a[i] * bb[j];
        }
        __syncthreads();
    }
#pragma unroll
    for (int i = 0; i < 8; i++) {
        int o = o0 + ty * 8 + i;
        float4 w0 = make_float4(acc[i][0], acc[i][1], acc[i][2], acc[i][3]);
        float4 w1 = make_float4(acc[i][4], acc[i][5], acc[i][6], acc[i][7]);
        *(float4*)&Y[o * SEQ + n0 + tx * 8]     = w0;
        *(float4*)&Y[o * SEQ + n0 + tx * 8 + 4] = w1;
    }
}

// ---------------- logits: S[n,m] = scale * sum_d Q[d,n] K[d,m] ----------------
__global__ void __launch_bounds__(256)
attn_kernel()
{
    int bh = blockIdx.z;
    int b = bh / NH, h = bh - b * NH;
    const float* Q  = g_q + (b * CDIM + h * DH) * SEQ;
    const float* Kp = g_k + (b * CDIM + h * DH) * SEQ;
    float* Ao = g_attn + (size_t)bh * SEQ * SEQ;

    __shared__ float Qs[16][132];
    __shared__ float Ks[16][132];

    int tid = threadIdx.x;
    int n0 = blockIdx.y * 128, m0 = blockIdx.x * 128;
    int ty = tid >> 4, tx = tid & 15;

    float acc[8][8];
#pragma unroll
    for (int i = 0; i < 8; i++)
#pragma unroll
        for (int j = 0; j < 8; j++) acc[i][j] = 0.f;

    int brow = tid >> 5, bcol = (tid & 31) << 2;

    for (int k0 = 0; k0 < DH; k0 += 16) {
#pragma unroll
        for (int r = 0; r < 2; r++) {
            *(float4*)&Qs[brow + r * 8][bcol] =
                *(const float4*)&Q[(k0 + brow + r * 8) * SEQ + n0 + bcol];
            *(float4*)&Ks[brow + r * 8][bcol] =
                *(const float4*)&Kp[(k0 + brow + r * 8) * SEQ + m0 + bcol];
        }
        __syncthreads();
#pragma unroll
        for (int kk = 0; kk < 16; kk++) {
            float a[8], bb[8];
            *(float4*)(a)     = *(float4*)&Qs[kk][ty * 8];
            *(float4*)(a + 4) = *(float4*)&Qs[kk][ty * 8 + 4];
            *(float4*)(bb)     = *(float4*)&Ks[kk][tx * 8];
            *(float4*)(bb + 4) = *(float4*)&Ks[kk][tx * 8 + 4];
#pragma unroll
            for (int i = 0; i < 8; i++)
#pragma unroll
                for (int j = 0; j < 8; j++) acc[i][j] += a[i] * bb[j];
        }
        __syncthreads();
    }
#pragma unroll
    for (int i = 0; i < 8; i++) {
        int n = n0 + ty * 8 + i;
        float4 w0 = make_float4(acc[i][0] * SCALEF, acc[i][1] * SCALEF,
                                acc[i][2] * SCALEF, acc[i][3] * SCALEF);
        float4 w1 = make_float4(acc[i][4] * SCALEF, acc[i][5] * SCALEF,
                                acc[i][6] * SCALEF, acc[i][7] * SCALEF);
        *(float4*)&Ao[(size_t)n * SEQ + m0 + tx * 8]     = w0;
        *(float4*)&Ao[(size_t)n * SEQ + m0 + tx * 8 + 4] = w1;
    }
}

// ---------------- row softmax in-place ----------------
__global__ void __launch_bounds__(256)
softmax_kernel()
{
    float* A = g_attn + ((size_t)blockIdx.y * SEQ + blockIdx.x) * SEQ;
    int tid = threadIdx.x;
    float4 v = *(float4*)&A[tid * 4];

    __shared__ float red1[32];
    __shared__ float red2[32];

    float m = fmaxf(fmaxf(v.x, v.y), fmaxf(v.z, v.w));
#pragma unroll
    for (int o = 16; o; o >>= 1) m = fmaxf(m, __shfl_xor_sync(0xffffffffu, m, o));
    if ((tid & 31) == 0) red1[tid >> 5] = m;
    __syncthreads();
    if (tid < 32) {
        float t = (tid < 8) ? red1[tid] : -3.4e38f;
#pragma unroll
        for (int o = 4; o; o >>= 1) t = fmaxf(t, __shfl_xor_sync(0xffffffffu, t, o));
        if (tid == 0) red1[0] = t;
    }
    __syncthreads();
    float mx = red1[0];

    float4 e;
    e.x = expf(v.x - mx); e.y = expf(v.y - mx);
    e.z = expf(v.z - mx); e.w = expf(v.w - mx);
    float s = e.x + e.y + e.z + e.w;
#pragma unroll
    for (int o = 16; o; o >>= 1) s += __shfl_xor_sync(0xffffffffu, s, o);
    if ((tid & 31) == 0) red2[tid >> 5] = s;
    __syncthreads();
    if (tid < 32) {
        float t = (tid < 8) ? red2[tid] : 0.f;
#pragma unroll
        for (int o = 4; o; o >>= 1) t += __shfl_xor_sync(0xffffffffu, t, o);
        if (tid == 0) red2[0] = t;
    }
    __syncthreads();
    float total = red2[0];

    float4 o4;
    o4.x = e.x / total; o4.y = e.y / total;
    o4.z = e.z / total; o4.w = e.w / total;
    *(float4*)&A[tid * 4] = o4;
}

// ---------------- top-k radix select ----------------
__global__ void zero_hist_kernel()
{
    int i = blockIdx.x * 256 + threadIdx.x;
    g_h1[i] = 0u;
    g_h2[i] = 0u;
}

__global__ void hist1_kernel()
{
    int i4 = blockIdx.x * 256 + threadIdx.x;     // 6291456 float4's
    int map = i4 >> 18;
    float4 v = *(const float4*)&g_attn[(size_t)i4 * 4];
    unsigned base = (unsigned)map << 16;
    atomicAdd(&g_h1[base + (__float_as_uint(v.x) >> 16)], 1u);
    atomicAdd(&g_h1[base + (__float_as_uint(v.y) >> 16)], 1u);
    atomicAdd(&g_h1[base + (__float_as_uint(v.z) >> 16)], 1u);
    atomicAdd(&g_h1[base + (__float_as_uint(v.w) >> 16)], 1u);
}

// find bucket (descending) where cumulative count crosses `target`.
__device__ void select_desc(const unsigned* h, unsigned target,
                            unsigned* outBucket, unsigned* outAbove)
{
    __shared__ unsigned psum[256];
    __shared__ unsigned ssum[256];
    int tid = threadIdx.x;
    unsigned s = 0;
    int base = tid * 256;
    for (int i = 0; i < 256; i++) s += h[base + i];
    psum[tid] = s;
    __syncthreads();
    if (tid == 0) {
        unsigned run = 0;
        for (int t = 255; t >= 0; t--) { ssum[t] = run; run += psum[t]; }
    }
    __syncthreads();
    if (ssum[tid] < target && ssum[tid] + psum[tid] >= target) {
        unsigned acc = ssum[tid];
        for (int i = 255; i >= 0; i--) {
            unsigned c = h[base + i];
            if (acc + c >= target) { *outBucket = (unsigned)(base + i); *outAbove = acc; break; }
            acc += c;
        }
    }
}

__global__ void select1_kernel()
{
    int map = blockIdx.x, tid = threadIdx.x;
    __shared__ unsigned rb, ra;
    select_desc(g_h1 + map * 65536, KTOP, &rb, &ra);
    __syncthreads();
    if (tid == 0) { g_H[map] = rb; g_above[map] = ra; }
}

__global__ void hist2_kernel()
{
    int i4 = blockIdx.x * 256 + threadIdx.x;
    int map = i4 >> 18;
    unsigned H = g_H[map];
    float4 v = *(const float4*)&g_attn[(size_t)i4 * 4];
    unsigned base = (unsigned)map << 16;
    unsigned bx = __float_as_uint(v.x);
    unsigned by = __float_as_uint(v.y);
    unsigned bz = __float_as_uint(v.z);
    unsigned bw = __float_as_uint(v.w);
    if ((bx >> 16) == H) atomicAdd(&g_h2[base + (bx & 0xFFFFu)], 1u);
    if ((by >> 16) == H) atomicAdd(&g_h2[base + (by & 0xFFFFu)], 1u);
    if ((bz >> 16) == H) atomicAdd(&g_h2[base + (bz & 0xFFFFu)], 1u);
    if ((bw >> 16) == H) atomicAdd(&g_h2[base + (bw & 0xFFFFu)], 1u);
}

__global__ void select2_kernel()
{
    int map = blockIdx.x, tid = threadIdx.x;
    __shared__ unsigned rb, ra;
    unsigned target = KTOP - g_above[map];
    select_desc(g_h2 + map * 65536, target, &rb, &ra);
    __syncthreads();
    if (tid == 0) {
        unsigned H = g_H[map];
        unsigned L = rb;
        g_thr[map] = (H << 16) | L;
        g_need[map] = (int)(target - ra);
        g_ceq[map] = (int)g_h2[map * 65536 + L];
    }
}

// resolve ties at the threshold value: lowest indices win (XLA top_k stable order)
__global__ void __launch_bounds__(1024)
eqsel_kernel()
{
    int map = blockIdx.x, tid = threadIdx.x;
    unsigned thr = g_thr[map];
    int need = g_need[map], ceq = g_ceq[map];
    if (need >= ceq) {
        if (tid == 0) g_cut[map] = 0x7FFFFFFF;
        return;
    }
    __shared__ int list[4096];
    __shared__ int cnt;
    if (tid == 0) cnt = 0;
    __syncthreads();
    const float* A = g_attn + ((size_t)map << 20);
    for (int i = tid; i < SEQ * SEQ; i += 1024) {
        if (__float_as_uint(A[i]) == thr) {
            int p = atomicAdd(&cnt, 1);
            if (p < 4096) list[p] = i;
        }
    }
    __syncthreads();
    int c = min(cnt, 4096);
    for (int i = tid; i < c; i += 1024) {
        int x = list[i];
        int r = 0;
        for (int j = 0; j < c; j++) r += (list[j] <= x);
        if (r == need) g_cut[map] = x;
    }
}

// ---------------- mask + causal + noncausal outputs ----------------
__global__ void maskout_kernel(float* __restrict__ out)
{
    int i4 = blockIdx.x * 256 + threadIdx.x;
    int map = i4 >> 18;
    unsigned thr = g_thr[map];
    int cut = g_cut[map];
    size_t e = (size_t)i4 * 4;
    int im = (int)(e & 0xFFFFFu);
    float4 a = *(const float4*)&g_attn[e];

    float4 msk, ac, an;
    unsigned b0 = __float_as_uint(a.x);
    unsigned b1 = __float_as_uint(a.y);
    unsigned b2 = __float_as_uint(a.z);
    unsigned b3 = __float_as_uint(a.w);
    bool s0 = (b0 > thr) || (b0 == thr && (im + 0) <= cut);
    bool s1 = (b1 > thr) || (b1 == thr && (im + 1) <= cut);
    bool s2 = (b2 > thr) || (b2 == thr && (im + 2) <= cut);
    bool s3 = (b3 > thr) || (b3 == thr && (im + 3) <= cut);
    msk.x = s0 ? 1.f : 0.f; msk.y = s1 ? 1.f : 0.f;
    msk.z = s2 ? 1.f : 0.f; msk.w = s3 ? 1.f : 0.f;
    ac.x = s0 ? a.x : 0.f;  ac.y = s1 ? a.y : 0.f;
    ac.z = s2 ? a.z : 0.f;  ac.w = s3 ? a.w : 0.f;
    an.x = s0 ? 0.f : a.x;  an.y = s1 ? 0.f : a.y;
    an.z = s2 ? 0.f : a.z;  an.w = s3 ? 0.f : a.w;

    *(float4*)&out[AC_OFF + e] = ac;
    *(float4*)&out[AN_OFF + e] = an;
    *(float4*)&out[BM_OFF + e] = msk;
}

// ---------------- attn_map = column means (deterministic 2-stage) ----------------
__global__ void colsum_kernel()
{
    int bh = blockIdx.y, nt = blockIdx.x, tid = threadIdx.x;
    const float* A = g_attn + ((size_t)bh << 20) + (size_t)nt * 64 * SEQ;
    float4 acc = make_float4(0.f, 0.f, 0.f, 0.f);
    for (int r = 0; r < 64; r++) {
        float4 v = *(const float4*)&A[(size_t)r * SEQ + tid * 4];
        acc.x += v.x; acc.y += v.y; acc.z += v.z; acc.w += v.w;
    }
    *(float4*)&g_part[((bh * 16 + nt) << 10) + tid * 4] = acc;
}

__global__ void mapfinal_kernel(float* __restrict__ out)
{
    int b = blockIdx.x, tid = threadIdx.x;
    float4 acc = make_float4(0.f, 0.f, 0.f, 0.f);
    for (int j = 0; j < 96; j++) {
        float4 v = *(const float4*)&g_part[((b * 96 + j) << 10) + tid * 4];
        acc.x += v.x; acc.y += v.y; acc.z += v.z; acc.w += v.w;
    }
    const float s = 1.f / 6144.f;
    float4 o4 = make_float4(acc.x * s, acc.y * s, acc.z * s, acc.w * s);
    *(float4*)&out[AM_OFF + b * SEQ + tid * 4] = o4;
}

// ---------------- out = attn @ v : C[d,n] = sum_m V[d,m] * A[n,m] ----------------
__global__ void __launch_bounds__(256)
av_kernel()
{
    int bh = blockIdx.z;
    int b = bh / NH, h = bh - b * NH;
    const float* A = g_attn + ((size_t)bh << 20);      // [n][m]
    const float* V = g_v + (b * CDIM + h * DH) * SEQ;  // [d][m]
    float* O = g_o + (b * CDIM + h * DH) * SEQ;        // [d][n]
    int n0 = blockIdx.x * 128;
    int tid = threadIdx.x;

    __shared__ float Vs[32][65];    // [m][d]
    __shared__ float Ans[32][129];  // [m][n]

    int ty = tid >> 4, tx = tid & 15;   // d = ty*4+i, n = tx*8+j
    float acc[4][8];
#pragma unroll
    for (int i = 0; i < 4; i++)
#pragma unroll
        for (int j = 0; j < 8; j++) acc[i][j] = 0.f;

    int lrow = tid >> 3, lcol = (tid & 7) << 2;

    for (int m0 = 0; m0 < SEQ; m0 += 32) {
        // V tile: 64 d x 32 m
#pragma unroll
        for (int p = 0; p < 2; p++) {
            int d = lrow + p * 32;
            float4 t = *(const float4*)&V[(size_t)d * SEQ + m0 + lcol];
            Vs[lcol + 0][d] = t.x; Vs[lcol + 1][d] = t.y;
            Vs[lcol + 2][d] = t.z; Vs[lcol + 3][d] = t.w;
        }
        // A tile: 128 n x 32 m
#pragma unroll
        for (int p = 0; p < 4; p++) {
            int n = lrow + p * 32;
            float4 t = *(const float4*)&A[(size_t)(n0 + n) * SEQ + m0 + lcol];
            Ans[lcol + 0][n] = t.x; Ans[lcol + 1][n] = t.y;
            Ans[lcol + 2][n] = t.z; Ans[lcol + 3][n] = t.w;
        }
        __syncthreads();
#pragma unroll
        for (int kk = 0; kk < 32; kk++) {
            float a[4], bn[8];
#pragma unroll
            for (int i = 0; i < 4; i++) a[i] = Vs[kk][ty * 4 + i];
#pragma unroll
            for (int j = 0; j < 8; j++) bn[j] = Ans[kk][tx * 8 + j];
#pragma unroll
            for (int i = 0; i < 4; i++)
#pragma unroll
                for (int j = 0; j < 8; j++) acc[i][j] += a[i] * bn[j];
        }
        __syncthreads();
    }
#pragma unroll
    for (int i = 0; i < 4; i++) {
        int d = ty * 4 + i;
        float4 w0 = make_float4(acc[i][0], acc[i][1], acc[i][2], acc[i][3]);
        float4 w1 = make_float4(acc[i][4], acc[i][5], acc[i][6], acc[i][7]);
        *(float4*)&O[(size_t)d * SEQ + n0 + tx * 8]     = w0;
        *(float4*)&O[(size_t)d * SEQ + n0 + tx * 8 + 4] = w1;
    }
}

// ---------------- output projection: P[o,n] = sum_c Wo[o,c]*X[c,n] + bo[o] ----------------
__global__ void __launch_bounds__(256)
oproj_kernel(const float* __restrict__ Wo, const float* __restrict__ bo,
             float* __restrict__ out)
{
    int b = blockIdx.z;
    const float* X = g_o + b * CDIM * SEQ;
    const float* W = Wo;

    __shared__ float As[16][132];
    __shared__ float Bs[16][132];

    int tid = threadIdx.x;
    int o0 = blockIdx.y * 128, n0 = blockIdx.x * 128;
    int ty = tid >> 4, tx = tid & 15;

    float acc[8][8];
#pragma unroll
    for (int i = 0; i < 8; i++)
#pragma unroll
        for (int j = 0; j < 8; j++) acc[i][j] = 0.f;

    int arow = tid >> 2, acol = (tid & 3) << 2;
    int brow = tid >> 5, bcol = (tid & 31) << 2;

    for (int k0 = 0; k0 < CDIM; k0 += 16) {
#pragma unroll
        for (int r = 0; r < 2; r++) {
            float4 w4 = *(const float4*)&W[(o0 + arow + r * 64) * CDIM + k0 + acol];
            As[acol + 0][arow + r * 64] = w4.x;
            As[acol + 1][arow + r * 64] = w4.y;
            As[acol + 2][arow + r * 64] = w4.z;
            As[acol + 3][arow + r * 64] = w4.w;
        }
#pragma unroll
        for (int r = 0; r < 2; r++) {
            *(float4*)&Bs[brow + r * 8][bcol] =
                *(const float4*)&X[(k0 + brow + r * 8) * SEQ + n0 + bcol];
        }
        __syncthreads();
#pragma unroll
        for (int kk = 0; kk < 16; kk++) {
            float a[8], bb[8];
            *(float4*)(a)     = *(float4*)&As[kk][ty * 8];
            *(float4*)(a + 4) = *(float4*)&As[kk][ty * 8 + 4];
            *(float4*)(bb)     = *(float4*)&Bs[kk][tx * 8];
            *(float4*)(bb + 4) = *(float4*)&Bs[kk][tx * 8 + 4];
#pragma unroll
            for (int i = 0; i < 8; i++)
#pragma unroll
                for (int j = 0; j < 8; j++) acc[i][j] += a[i] * bb[j];
        }
        __syncthreads();
    }
#pragma unroll
    for (int i = 0; i < 8; i++) {
        int o = o0 + ty * 8 + i;
        float bias = __ldg(&bo[o]);
        float4 w0 = make_float4(acc[i][0] + bias, acc[i][1] + bias,
                                acc[i][2] + bias, acc[i][3] + bias);
        float4 w1 = make_float4(acc[i][4] + bias, acc[i][5] + bias,
                                acc[i][6] + bias, acc[i][7] + bias);
        *(float4*)&out[OP_OFF + (size_t)(b * CDIM + o) * SEQ + n0 + tx * 8]     = w0;
        *(float4*)&out[OP_OFF + (size_t)(b * CDIM + o) * SEQ + n0 + tx * 8 + 4] = w1;
    }
}

// ---------------- launch ----------------
extern "C" void kernel_launch(void* const* d_in, const int* in_sizes, int n_in,
                              void* d_out, int out_size)
{
    (void)in_sizes; (void)n_in; (void)out_size;
    const float* query   = (const float*)d_in[0];
    const float* context = (const float*)d_in[1];
    const float* Wq = (const float*)d_in[2];
    const float* Wk = (const float*)d_in[3];
    const float* Wv = (const float*)d_in[4];
    const float* Wo = (const float*)d_in[5];
    const float* bo = (const float*)d_in[6];
    float* out = (float*)d_out;

    proj_kernel<<<dim3(8, 3, 12), 256>>>(query, context, Wq, Wk, Wv);
    attn_kernel<<<dim3(8, 8, 24), 256>>>();
    softmax_kernel<<<dim3(1024, 24), 256>>>();

    zero_hist_kernel<<<6144, 256>>>();
    hist1_kernel<<<24576, 256>>>();
    select1_kernel<<<24, 256>>>();
    hist2_kernel<<<24576, 256>>>();
    select2_kernel<<<24, 256>>>();
    eqsel_kernel<<<24, 1024>>>();

    maskout_kernel<<<24576, 256>>>(out);
    colsum_kernel<<<dim3(16, 24), 256>>>();
    mapfinal_kernel<<<4, 256>>>(out);

    av_kernel<<<dim3(8, 1, 24), 256>>>();
    oproj_kernel<<<dim3(8, 3, 4), 256>>>(Wo, bo, out);
}

// round 5
// speedup vs baseline: 2.9266x; 2.9266x over previous
#include <cuda_runtime.h>
#include <cstdint>
#include <string.h>
#include <math.h>

// ---------------- problem constants ----------------
#define NB    4
#define NH    6
#define NMAP  24          // NB*NH
#define SEQ   1024        // H*W
#define DH    64
#define CDIM  384
#define KTOP  734003u     // int(0.7 * 1024 * 1024)
#define SCALEF 0.125f     // 64^-0.5

// output offsets (element counts, float32)
#define OP_OFF 0
#define AM_OFF 1572864
#define AC_OFF 1576960
#define AN_OFF 26742784
#define BM_OFF 51908608

// ---------------- scratch (no cudaMalloc allowed; device globals) ----------------
__device__ float g_q[NB * CDIM * SEQ];
__device__ float g_k[NB * CDIM * SEQ];
__device__ float g_v[NB * CDIM * SEQ];
__device__ float g_o[NB * CDIM * SEQ];
__device__ float g_attn[(size_t)NMAP * SEQ * SEQ];   // 96 MB
__device__ unsigned g_hA[NMAP * 4096];
__device__ unsigned g_hB[NMAP * 1024];
__device__ unsigned g_hC[NMAP * 1024];
__device__ unsigned g_D1[NMAP];
__device__ unsigned g_t2[NMAP];      // remaining target after digit 1
__device__ unsigned g_D2[NMAP];
__device__ unsigned g_t3[NMAP];      // remaining target after digit 2
__device__ unsigned g_thr[NMAP];
__device__ int g_cut[NMAP];
__device__ float g_part[NMAP * 64 * SEQ];

// ---------------- packed fp32x2 FMA (full-rate fp32 on Blackwell) ----------------
__device__ __forceinline__ float2 ffma2(float2 a, float2 b, float2 c)
{
    unsigned long long A, B, C, D;
    memcpy(&A, &a, 8); memcpy(&B, &b, 8); memcpy(&C, &c, 8);
    asm("fma.rn.f32x2 %0, %1, %2, %3;" : "=l"(D) : "l"(A), "l"(B), "l"(C));
    float2 r; memcpy(&r, &D, 8); return r;
}

// ---------------- zero small scratch ----------------
__global__ void zero_kernel()
{
    int i = blockIdx.x * 1024 + threadIdx.x;
    if (i < NMAP * 4096) g_hA[i] = 0u;
    int j = i - NMAP * 4096;
    if (j >= 0 && j < NMAP * 1024) g_hB[j] = 0u;
    int k = j - NMAP * 1024;
    if (k >= 0 && k < NMAP * 1024) g_hC[k] = 0u;
}

// ---------------- QKV projection ----------------
__global__ void __launch_bounds__(256)
proj_kernel(const float* __restrict__ qin, const float* __restrict__ cin,
            const float* __restrict__ Wq, const float* __restrict__ Wk,
            const float* __restrict__ Wv)
{
    int bz = blockIdx.z;
    int b = bz / 3, p = bz - b * 3;
    const float* X = (p == 0 ? qin : cin) + b * CDIM * SEQ;
    const float* W = (p == 0 ? Wq : (p == 1 ? Wk : Wv));
    float* Y = (p == 0 ? g_q : (p == 1 ? g_k : g_v)) + b * CDIM * SEQ;

    __shared__ float2 As2[16][132];
    __shared__ float  Bs[16][132];

    int tid = threadIdx.x;
    int o0 = blockIdx.y * 128, n0 = blockIdx.x * 128;
    int ty = tid >> 4, tx = tid & 15;

    float2 acc2[8][4];
#pragma unroll
    for (int i = 0; i < 8; i++)
#pragma unroll
        for (int j = 0; j < 4; j++) acc2[i][j] = make_float2(0.f, 0.f);

    int arow = tid >> 2, acol = (tid & 3) << 2;
    int brow = tid >> 5, bcol = (tid & 31) << 2;

    for (int k0 = 0; k0 < CDIM; k0 += 16) {
#pragma unroll
        for (int r = 0; r < 2; r++) {
            float4 w4 = *(const float4*)&W[(o0 + arow + r * 64) * CDIM + k0 + acol];
            As2[acol + 0][arow + r * 64] = make_float2(w4.x, w4.x);
            As2[acol + 1][arow + r * 64] = make_float2(w4.y, w4.y);
            As2[acol + 2][arow + r * 64] = make_float2(w4.z, w4.z);
            As2[acol + 3][arow + r * 64] = make_float2(w4.w, w4.w);
        }
#pragma unroll
        for (int r = 0; r < 2; r++) {
            *(float4*)&Bs[brow + r * 8][bcol] =
                *(const float4*)&X[(k0 + brow + r * 8) * SEQ + n0 + bcol];
        }
        __syncthreads();
#pragma unroll
        for (int kk = 0; kk < 16; kk++) {
            float2 a2[8];
            *(float4*)&a2[0] = *(float4*)&As2[kk][ty * 8];
            *(float4*)&a2[2] = *(float4*)&As2[kk][ty * 8 + 2];
            *(float4*)&a2[4] = *(float4*)&As2[kk][ty * 8 + 4];
            *(float4*)&a2[6] = *(float4*)&As2[kk][ty * 8 + 6];
            float4 b01 = *(float4*)&Bs[kk][tx * 8];
            float4 b23 = *(float4*)&Bs[kk][tx * 8 + 4];
            float2 bp[4] = { make_float2(b01.x, b01.y), make_float2(b01.z, b01.w),
                             make_float2(b23.x, b23.y), make_float2(b23.z, b23.w) };
#pragma unroll
            for (int i = 0; i < 8; i++)
#pragma unroll
                for (int pp = 0; pp < 4; pp++)
                    acc2[i][pp] = ffma2(a2[i], bp[pp], acc2[i][pp]);
        }
        __syncthreads();
    }
#pragma unroll
    for (int i = 0; i < 8; i++) {
        int o = o0 + ty * 8 + i;
        float4 w0 = make_float4(acc2[i][0].x, acc2[i][0].y, acc2[i][1].x, acc2[i][1].y);
        float4 w1 = make_float4(acc2[i][2].x, acc2[i][2].y, acc2[i][3].x, acc2[i][3].y);
        *(float4*)&Y[o * SEQ + n0 + tx * 8]     = w0;
        *(float4*)&Y[o * SEQ + n0 + tx * 8 + 4] = w1;
    }
}

// ---------------- logits ----------------
__global__ void __launch_bounds__(256)
attn_kernel()
{
    int bh = blockIdx.z;
    int b = bh / NH, h = bh - b * NH;
    const float* Q  = g_q + (b * CDIM + h * DH) * SEQ;
    const float* Kp = g_k + (b * CDIM + h * DH) * SEQ;
    float* Ao = g_attn + (size_t)bh * SEQ * SEQ;

    __shared__ float2 Qs2[16][132];
    __shared__ float  Ks[16][132];

    int tid = threadIdx.x;
    int n0 = blockIdx.y * 128, m0 = blockIdx.x * 128;
    int ty = tid >> 4, tx = tid & 15;

    float2 acc2[8][4];
#pragma unroll
    for (int i = 0; i < 8; i++)
#pragma unroll
        for (int j = 0; j < 4; j++) acc2[i][j] = make_float2(0.f, 0.f);

    int brow = tid >> 5, bcol = (tid & 31) << 2;

    for (int k0 = 0; k0 < DH; k0 += 16) {
#pragma unroll
        for (int r = 0; r < 2; r++) {
            float4 t = *(const float4*)&Q[(k0 + brow + r * 8) * SEQ + n0 + bcol];
            Qs2[brow + r * 8][bcol + 0] = make_float2(t.x, t.x);
            Qs2[brow + r * 8][bcol + 1] = make_float2(t.y, t.y);
            Qs2[brow + r * 8][bcol + 2] = make_float2(t.z, t.z);
            Qs2[brow + r * 8][bcol + 3] = make_float2(t.w, t.w);
            *(float4*)&Ks[brow + r * 8][bcol] =
                *(const float4*)&Kp[(k0 + brow + r * 8) * SEQ + m0 + bcol];
        }
        __syncthreads();
#pragma unroll
        for (int kk = 0; kk < 16; kk++) {
            float2 a2[8];
            *(float4*)&a2[0] = *(float4*)&Qs2[kk][ty * 8];
            *(float4*)&a2[2] = *(float4*)&Qs2[kk][ty * 8 + 2];
            *(float4*)&a2[4] = *(float4*)&Qs2[kk][ty * 8 + 4];
            *(float4*)&a2[6] = *(float4*)&Qs2[kk][ty * 8 + 6];
            float4 b01 = *(float4*)&Ks[kk][tx * 8];
            float4 b23 = *(float4*)&Ks[kk][tx * 8 + 4];
            float2 bp[4] = { make_float2(b01.x, b01.y), make_float2(b01.z, b01.w),
                             make_float2(b23.x, b23.y), make_float2(b23.z, b23.w) };
#pragma unroll
            for (int i = 0; i < 8; i++)
#pragma unroll
                for (int pp = 0; pp < 4; pp++)
                    acc2[i][pp] = ffma2(a2[i], bp[pp], acc2[i][pp]);
        }
        __syncthreads();
    }
#pragma unroll
    for (int i = 0; i < 8; i++) {
        int n = n0 + ty * 8 + i;
        float4 w0 = make_float4(acc2[i][0].x * SCALEF, acc2[i][0].y * SCALEF,
                                acc2[i][1].x * SCALEF, acc2[i][1].y * SCALEF);
        float4 w1 = make_float4(acc2[i][2].x * SCALEF, acc2[i][2].y * SCALEF,
                                acc2[i][3].x * SCALEF, acc2[i][3].y * SCALEF);
        *(float4*)&Ao[(size_t)n * SEQ + m0 + tx * 8]     = w0;
        *(float4*)&Ao[(size_t)n * SEQ + m0 + tx * 8 + 4] = w1;
    }
}

// ---------------- softmax (warp per row) fused with 12-bit histogram ----------------
__global__ void __launch_bounds__(256)
softhist_kernel()
{
    int map = blockIdx.y;
    __shared__ unsigned hist[4096];
    int tid = threadIdx.x;
    for (int i = tid; i < 4096; i += 256) hist[i] = 0u;
    __syncthreads();

    int warp = tid >> 5, lane = tid & 31;
    float* base = g_attn + ((size_t)map << 20);

    for (int rr = 0; rr < 4; rr++) {
        int row = blockIdx.x * 32 + warp * 4 + rr;
        float* A = base + (size_t)row * SEQ;
        float4 v[8];
        float mx = -3.4e38f;
#pragma unroll
        for (int j = 0; j < 8; j++) {
            v[j] = *(float4*)&A[j * 128 + lane * 4];
            mx = fmaxf(mx, fmaxf(fmaxf(v[j].x, v[j].y), fmaxf(v[j].z, v[j].w)));
        }
#pragma unroll
        for (int o = 16; o; o >>= 1) mx = fmaxf(mx, __shfl_xor_sync(0xffffffffu, mx, o));
        float s = 0.f;
#pragma unroll
        for (int j = 0; j < 8; j++) {
            v[j].x = expf(v[j].x - mx); v[j].y = expf(v[j].y - mx);
            v[j].z = expf(v[j].z - mx); v[j].w = expf(v[j].w - mx);
            s += (v[j].x + v[j].y) + (v[j].z + v[j].w);
        }
#pragma unroll
        for (int o = 16; o; o >>= 1) s += __shfl_xor_sync(0xffffffffu, s, o);
#pragma unroll
        for (int j = 0; j < 8; j++) {
            float4 o4;
            o4.x = v[j].x / s; o4.y = v[j].y / s;
            o4.z = v[j].z / s; o4.w = v[j].w / s;
            *(float4*)&A[j * 128 + lane * 4] = o4;
            atomicAdd(&hist[__float_as_uint(o4.x) >> 20], 1u);
            atomicAdd(&hist[__float_as_uint(o4.y) >> 20], 1u);
            atomicAdd(&hist[__float_as_uint(o4.z) >> 20], 1u);
            atomicAdd(&hist[__float_as_uint(o4.w) >> 20], 1u);
        }
    }
    __syncthreads();
    for (int i = tid; i < 4096; i += 256) {
        unsigned c = hist[i];
        if (c) atomicAdd(&g_hA[map * 4096 + i], c);
    }
}

// ---------------- select digit 1 (4096 bins, descending) ----------------
__global__ void select1_kernel()
{
    int map = blockIdx.x, tid = threadIdx.x;
    __shared__ unsigned psum[256], ssum[256];
    __shared__ unsigned rD, rA;
    const unsigned* h = g_hA + map * 4096;
    unsigned s = 0;
    int b0 = tid * 16;
    for (int i = 0; i < 16; i++) s += h[b0 + i];
    psum[tid] = s;
    __syncthreads();
    if (tid == 0) {
        unsigned run = 0;
        for (int t = 255; t >= 0; t--) { ssum[t] = run; run += psum[t]; }
    }
    __syncthreads();
    unsigned target = KTOP;
    if (ssum[tid] < target && ssum[tid] + psum[tid] >= target) {
        unsigned acc = ssum[tid];
        for (int i = 15; i >= 0; i--) {
            unsigned c = h[b0 + i];
            if (acc + c >= target) { rD = (unsigned)(b0 + i); rA = acc; break; }
            acc += c;
        }
    }
    __syncthreads();
    if (tid == 0) { g_D1[map] = rD; g_t2[map] = target - rA; }
}

// ---------------- scan 2: histogram middle 10 bits of D1-bucket elements ----------------
__global__ void __launch_bounds__(256)
scan2_kernel()
{
    int map = blockIdx.y, tid = threadIdx.x;
    unsigned D1 = g_D1[map];
    __shared__ unsigned hist[1024];
    for (int i = tid; i < 1024; i += 256) hist[i] = 0u;
    __syncthreads();

    const float* A = g_attn + ((size_t)map << 20);
    int fbase = blockIdx.x * 4096;
#pragma unroll 4
    for (int i = 0; i < 16; i++) {
        const float4 v = *(const float4*)&A[(size_t)(fbase + i * 256 + tid) * 4];
        unsigned k0 = __float_as_uint(v.x), k1 = __float_as_uint(v.y);
        unsigned k2 = __float_as_uint(v.z), k3 = __float_as_uint(v.w);
        if ((k0 >> 20) == D1) atomicAdd(&hist[(k0 >> 10) & 1023], 1u);
        if ((k1 >> 20) == D1) atomicAdd(&hist[(k1 >> 10) & 1023], 1u);
        if ((k2 >> 20) == D1) atomicAdd(&hist[(k2 >> 10) & 1023], 1u);
        if ((k3 >> 20) == D1) atomicAdd(&hist[(k3 >> 10) & 1023], 1u);
    }
    __syncthreads();
    for (int i = tid; i < 1024; i += 256) {
        unsigned c = hist[i];
        if (c) atomicAdd(&g_hB[map * 1024 + i], c);
    }
}

// ---------------- select digit 2 ----------------
__global__ void select2_kernel()
{
    int map = blockIdx.x, tid = threadIdx.x;   // 1024 threads
    __shared__ unsigned hist[1024];
    hist[tid] = g_hB[map * 1024 + tid];
    __syncthreads();
    if (tid == 0) {
        unsigned target = g_t2[map];
        unsigned acc = 0;
        for (int i = 1023; i >= 0; i--) {
            unsigned c = hist[i];
            if (acc + c >= target) { g_D2[map] = (unsigned)i; g_t3[map] = target - acc; break; }
            acc += c;
        }
    }
}

// ---------------- scan 3: histogram low 10 bits of D1:D2-bucket elements ----------------
__global__ void __launch_bounds__(256)
scan3_kernel()
{
    int map = blockIdx.y, tid = threadIdx.x;
    unsigned key22 = (g_D1[map] << 10) | g_D2[map];
    __shared__ unsigned hist[1024];
    for (int i = tid; i < 1024; i += 256) hist[i] = 0u;
    __syncthreads();

    const float* A = g_attn + ((size_t)map << 20);
    int fbase = blockIdx.x * 4096;
#pragma unroll 4
    for (int i = 0; i < 16; i++) {
        const float4 v = *(const float4*)&A[(size_t)(fbase + i * 256 + tid) * 4];
        unsigned k0 = __float_as_uint(v.x), k1 = __float_as_uint(v.y);
        unsigned k2 = __float_as_uint(v.z), k3 = __float_as_uint(v.w);
        if ((k0 >> 10) == key22) atomicAdd(&hist[k0 & 1023], 1u);
        if ((k1 >> 10) == key22) atomicAdd(&hist[k1 & 1023], 1u);
        if ((k2 >> 10) == key22) atomicAdd(&hist[k2 & 1023], 1u);
        if ((k3 >> 10) == key22) atomicAdd(&hist[k3 & 1023], 1u);
    }
    __syncthreads();
    for (int i = tid; i < 1024; i += 256) {
        unsigned c = hist[i];
        if (c) atomicAdd(&g_hC[map * 1024 + i], c);
    }
}

// ---------------- final: select digit 3, resolve ties by lowest index ----------------
__global__ void __launch_bounds__(1024)
final_select_kernel()
{
    int map = blockIdx.x, tid = threadIdx.x;
    __shared__ unsigned hist[1024];
    __shared__ unsigned sD3, sA3;
    __shared__ int eqlist[4096];
    __shared__ int eqcnt, scut;

    hist[tid] = g_hC[map * 1024 + tid];
    if (tid == 0) eqcnt = 0;
    __syncthreads();
    unsigned target = g_t3[map];
    if (tid == 0) {
        unsigned acc = 0;
        for (int i = 1023; i >= 0; i--) {
            unsigned c = hist[i];
            if (acc + c >= target) { sD3 = (unsigned)i; sA3 = acc; break; }
            acc += c;
        }
    }
    __syncthreads();
    unsigned thr = (g_D1[map] << 20) | (g_D2[map] << 10) | sD3;
    int need = (int)(target - sA3);
    int ceq = (int)hist[sD3];
    int cut;
    if (need >= ceq) {
        cut = 0x7FFFFFFF;
    } else {
        const float* A = g_attn + ((size_t)map << 20);
        for (int i = tid; i < SEQ * SEQ; i += 1024) {
            if (__float_as_uint(A[i]) == thr) {
                int p = atomicAdd(&eqcnt, 1);
                if (p < 4096) eqlist[p] = i;
            }
        }
        __syncthreads();
        int c2 = min(eqcnt, 4096);
        for (int i = tid; i < c2; i += 1024) {
            int x = eqlist[i];
            int r = 0;
            for (int j = 0; j < c2; j++) r += (eqlist[j] <= x);
            if (r == need) scut = x;
        }
        __syncthreads();
        cut = scut;
    }
    if (tid == 0) { g_thr[map] = thr; g_cut[map] = cut; }
}

// ---------------- mask outputs + column sums (fused) ----------------
__global__ void __launch_bounds__(256)
maskout_colsum_kernel(float* __restrict__ out)
{
    int map = blockIdx.y, tid = threadIdx.x;
    unsigned thr = g_thr[map];
    int cut = g_cut[map];
    const float* A = g_attn + ((size_t)map << 20);
    int col = tid * 4;
    float4 sum = make_float4(0.f, 0.f, 0.f, 0.f);
    for (int r = 0; r < 16; r++) {
        int row = blockIdx.x * 16 + r;
        int im = row * SEQ + col;
        size_t e = ((size_t)map << 20) + (size_t)im;
        float4 a = *(const float4*)&A[im];
        unsigned b0 = __float_as_uint(a.x), b1 = __float_as_uint(a.y);
        unsigned b2 = __float_as_uint(a.z), b3 = __float_as_uint(a.w);
        bool s0 = (b0 > thr) || (b0 == thr && (im + 0) <= cut);
        bool s1 = (b1 > thr) || (b1 == thr && (im + 1) <= cut);
        bool s2 = (b2 > thr) || (b2 == thr && (im + 2) <= cut);
        bool s3 = (b3 > thr) || (b3 == thr && (im + 3) <= cut);
        float4 msk = make_float4(s0 ? 1.f : 0.f, s1 ? 1.f : 0.f, s2 ? 1.f : 0.f, s3 ? 1.f : 0.f);
        float4 ac  = make_float4(s0 ? a.x : 0.f, s1 ? a.y : 0.f, s2 ? a.z : 0.f, s3 ? a.w : 0.f);
        float4 an  = make_float4(s0 ? 0.f : a.x, s1 ? 0.f : a.y, s2 ? 0.f : a.z, s3 ? 0.f : a.w);
        *(float4*)&out[AC_OFF + e] = ac;
        *(float4*)&out[AN_OFF + e] = an;
        *(float4*)&out[BM_OFF + e] = msk;
        sum.x += a.x; sum.y += a.y; sum.z += a.z; sum.w += a.w;
    }
    *(float4*)&g_part[((map * 64 + blockIdx.x) << 10) + col] = sum;
}

__global__ void mapfinal_kernel(float* __restrict__ out)
{
    int b = blockIdx.x, tid = threadIdx.x;
    float4 acc = make_float4(0.f, 0.f, 0.f, 0.f);
    for (int j = 0; j < 384; j++) {
        float4 v = *(const float4*)&g_part[((b * 384 + j) << 10) + tid * 4];
        acc.x += v.x; acc.y += v.y; acc.z += v.z; acc.w += v.w;
    }
    const float s = 1.f / 6144.f;
    *(float4*)&out[AM_OFF + b * SEQ + tid * 4] =
        make_float4(acc.x * s, acc.y * s, acc.z * s, acc.w * s);
}

// ---------------- attn @ V ----------------
__global__ void __launch_bounds__(256)
av_kernel()
{
    int bh = blockIdx.z;
    int b = bh / NH, h = bh - b * NH;
    const float* A = g_attn + ((size_t)bh << 20);
    const float* V = g_v + (b * CDIM + h * DH) * SEQ;
    float* O = g_o + (b * CDIM + h * DH) * SEQ;
    int n0 = blockIdx.x * 128;
    int tid = threadIdx.x;

    __shared__ float2 Vs2[32][68];
    __shared__ float  Ans[32][130];

    int ty = tid >> 4, tx = tid & 15;
    float2 acc2[4][4];
#pragma unroll
    for (int i = 0; i < 4; i++)
#pragma unroll
        for (int j = 0; j < 4; j++) acc2[i][j] = make_float2(0.f, 0.f);

    int lrow = tid >> 3, lcol = (tid & 7) << 2;

    for (int m0 = 0; m0 < SEQ; m0 += 32) {
#pragma unroll
        for (int p = 0; p < 2; p++) {
            int d = lrow + p * 32;
            float4 t = *(const float4*)&V[(size_t)d * SEQ + m0 + lcol];
            Vs2[lcol + 0][d] = make_float2(t.x, t.x);
            Vs2[lcol + 1][d] = make_float2(t.y, t.y);
            Vs2[lcol + 2][d] = make_float2(t.z, t.z);
            Vs2[lcol + 3][d] = make_float2(t.w, t.w);
        }
#pragma unroll
        for (int p = 0; p < 4; p++) {
            int n = lrow + p * 32;
            float4 t = *(const float4*)&A[(size_t)(n0 + n) * SEQ + m0 + lcol];
            Ans[lcol + 0][n] = t.x; Ans[lcol + 1][n] = t.y;
            Ans[lcol + 2][n] = t.z; Ans[lcol + 3][n] = t.w;
        }
        __syncthreads();
#pragma unroll
        for (int kk = 0; kk < 32; kk++) {
            float2 a2[4];
            *(float4*)&a2[0] = *(float4*)&Vs2[kk][ty * 4];
            *(float4*)&a2[2] = *(float4*)&Vs2[kk][ty * 4 + 2];
            float2 bp[4];
#pragma unroll
            for (int p = 0; p < 4; p++) bp[p] = *(float2*)&Ans[kk][tx * 8 + 2 * p];
#pragma unroll
            for (int i = 0; i < 4; i++)
#pragma unroll
                for (int p = 0; p < 4; p++)
                    acc2[i][p] = ffma2(a2[i], bp[p], acc2[i][p]);
        }
        __syncthreads();
    }
#pragma unroll
    for (int i = 0; i < 4; i++) {
        int d = ty * 4 + i;
        float4 w0 = make_float4(acc2[i][0].x, acc2[i][0].y, acc2[i][1].x, acc2[i][1].y);
        float4 w1 = make_float4(acc2[i][2].x, acc2[i][2].y, acc2[i][3].x, acc2[i][3].y);
        *(float4*)&O[(size_t)d * SEQ + n0 + tx * 8]     = w0;
        *(float4*)&O[(size_t)d * SEQ + n0 + tx * 8 + 4] = w1;
    }
}

// ---------------- output projection ----------------
__global__ void __launch_bounds__(256)
oproj_kernel(const float* __restrict__ Wo, const float* __restrict__ bo,
             float* __restrict__ out)
{
    int b = blockIdx.z;
    const float* X = g_o + b * CDIM * SEQ;

    __shared__ float2 As2[16][132];
    __shared__ float  Bs[16][132];

    int tid = threadIdx.x;
    int o0 = blockIdx.y * 128, n0 = blockIdx.x * 128;
    int ty = tid >> 4, tx = tid & 15;

    float2 acc2[8][4];
#pragma unroll
    for (int i = 0; i < 8; i++)
#pragma unroll
        for (int j = 0; j < 4; j++) acc2[i][j] = make_float2(0.f, 0.f);

    int arow = tid >> 2, acol = (tid & 3) << 2;
    int brow = tid >> 5, bcol = (tid & 31) << 2;

    for (int k0 = 0; k0 < CDIM; k0 += 16) {
#pragma unroll
        for (int r = 0; r < 2; r++) {
            float4 w4 = *(const float4*)&Wo[(o0 + arow + r * 64) * CDIM + k0 + acol];
            As2[acol + 0][arow + r * 64] = make_float2(w4.x, w4.x);
            As2[acol + 1][arow + r * 64] = make_float2(w4.y, w4.y);
            As2[acol + 2][arow + r * 64] = make_float2(w4.z, w4.z);
            As2[acol + 3][arow + r * 64] = make_float2(w4.w, w4.w);
        }
#pragma unroll
        for (int r = 0; r < 2; r++) {
            *(float4*)&Bs[brow + r * 8][bcol] =
                *(const float4*)&X[(k0 + brow + r * 8) * SEQ + n0 + bcol];
        }
        __syncthreads();
#pragma unroll
        for (int kk = 0; kk < 16; kk++) {
            float2 a2[8];
            *(float4*)&a2[0] = *(float4*)&As2[kk][ty * 8];
            *(float4*)&a2[2] = *(float4*)&As2[kk][ty * 8 + 2];
            *(float4*)&a2[4] = *(float4*)&As2[kk][ty * 8 + 4];
            *(float4*)&a2[6] = *(float4*)&As2[kk][ty * 8 + 6];
            float4 b01 = *(float4*)&Bs[kk][tx * 8];
            float4 b23 = *(float4*)&Bs[kk][tx * 8 + 4];
            float2 bp[4] = { make_float2(b01.x, b01.y), make_float2(b01.z, b01.w),
                             make_float2(b23.x, b23.y), make_float2(b23.z, b23.w) };
#pragma unroll
            for (int i = 0; i < 8; i++)
#pragma unroll
                for (int pp = 0; pp < 4; pp++)
                    acc2[i][pp] = ffma2(a2[i], bp[pp], acc2[i][pp]);
        }
        __syncthreads();
    }
#pragma unroll
    for (int i = 0; i < 8; i++) {
        int o = o0 + ty * 8 + i;
        float bias = __ldg(&bo[o]);
        float4 w0 = make_float4(acc2[i][0].x + bias, acc2[i][0].y + bias,
                                acc2[i][1].x + bias, acc2[i][1].y + bias);
        float4 w1 = make_float4(acc2[i][2].x + bias, acc2[i][2].y + bias,
                                acc2[i][3].x + bias, acc2[i][3].y + bias);
        *(float4*)&out[OP_OFF + (size_t)(b * CDIM + o) * SEQ + n0 + tx * 8]     = w0;
        *(float4*)&out[OP_OFF + (size_t)(b * CDIM + o) * SEQ + n0 + tx * 8 + 4] = w1;
    }
}

// ---------------- launch ----------------
extern "C" void kernel_launch(void* const* d_in, const int* in_sizes, int n_in,
                              void* d_out, int out_size)
{
    (void)in_sizes; (void)n_in; (void)out_size;
    const float* query   = (const float*)d_in[0];
    const float* context = (const float*)d_in[1];
    const float* Wq = (const float*)d_in[2];
    const float* Wk = (const float*)d_in[3];
    const float* Wv = (const float*)d_in[4];
    const float* Wo = (const float*)d_in[5];
    const float* bo = (const float*)d_in[6];
    float* out = (float*)d_out;

    zero_kernel<<<145, 1024>>>();
    proj_kernel<<<dim3(8, 3, 12), 256>>>(query, context, Wq, Wk, Wv);
    attn_kernel<<<dim3(8, 8, 24), 256>>>();
    softhist_kernel<<<dim3(32, 24), 256>>>();
    select1_kernel<<<24, 256>>>();
    scan2_kernel<<<dim3(64, 24), 256>>>();
    select2_kernel<<<24, 1024>>>();
    scan3_kernel<<<dim3(64, 24), 256>>>();
    final_select_kernel<<<24, 1024>>>();
    maskout_colsum_kernel<<<dim3(64, 24), 256>>>(out);
    mapfinal_kernel<<<4, 256>>>(out);
    av_kernel<<<dim3(8, 1, 24), 256>>>();
    oproj_kernel<<<dim3(8, 3, 4), 256>>>(Wo, bo, out);
}

// round 7
// speedup vs baseline: 3.5837x; 1.2245x over previous
#include <cuda_runtime.h>
#include <cstdint>
#include <string.h>
#include <math.h>

// ---------------- problem constants ----------------
#define NB    4
#define NH    6
#define NMAP  24          // NB*NH
#define SEQ   1024        // H*W
#define DH    64
#define CDIM  384
#define KTOP  734003u     // int(0.7 * 1024 * 1024)
#define SCALEF 0.125f     // 64^-0.5

// output offsets (element counts, float32)
#define OP_OFF 0
#define AM_OFF 1572864
#define AC_OFF 1576960
#define AN_OFF 26742784
#define BM_OFF 51908608

// ---------------- scratch (device globals) ----------------
__device__ float g_q[NB * CDIM * SEQ];
__device__ float g_k[NB * CDIM * SEQ];
__device__ float g_v[NB * CDIM * SEQ];
__device__ float g_o[NB * CDIM * SEQ];
__device__ float g_attn[(size_t)NMAP * SEQ * SEQ];   // 96 MB
__device__ unsigned g_hA[NMAP * 4096];
__device__ unsigned g_hB[NMAP * 1024];
__device__ unsigned g_hC[NMAP * 1024];
__device__ unsigned g_D1[NMAP];
__device__ unsigned g_t2[NMAP];
__device__ unsigned g_D2[NMAP];
__device__ unsigned g_t3[NMAP];
__device__ unsigned g_thr[NMAP];
__device__ int g_need[NMAP];
__device__ int g_cut[NMAP];
__device__ unsigned g_eqcnt[NMAP];
__device__ int g_eq[NMAP * 4096];
__device__ float g_part[NMAP * 64 * SEQ];

// ---------------- packed fp32x2 FMA ----------------
__device__ __forceinline__ float2 ffma2(float2 a, float2 b, float2 c)
{
    unsigned long long A, B, C, D;
    memcpy(&A, &a, 8); memcpy(&B, &b, 8); memcpy(&C, &c, 8);
    asm("fma.rn.f32x2 %0, %1, %2, %3;" : "=l"(D) : "l"(A), "l"(B), "l"(C));
    float2 r; memcpy(&r, &D, 8); return r;
}

__device__ __forceinline__ void stcs4(float* p, float4 v)
{
    asm volatile("st.global.cs.v4.f32 [%0], {%1,%2,%3,%4};"
                 :: "l"(p), "f"(v.x), "f"(v.y), "f"(v.z), "f"(v.w) : "memory");
}

// ---------------- zero small scratch ----------------
__global__ void zero_kernel()
{
    int i = blockIdx.x * 1024 + threadIdx.x;
    if (i < NMAP * 4096) g_hA[i] = 0u;
    int j = i - NMAP * 4096;
    if (j >= 0 && j < NMAP * 1024) g_hB[j] = 0u;
    int k = j - NMAP * 1024;
    if (k >= 0 && k < NMAP * 1024) g_hC[k] = 0u;
    int l = k - NMAP * 1024;
    if (l >= 0 && l < NMAP) g_eqcnt[l] = 0u;
}

// ---------------- QKV projection ----------------
__global__ void __launch_bounds__(256)
proj_kernel(const float* __restrict__ qin, const float* __restrict__ cin,
            const float* __restrict__ Wq, const float* __restrict__ Wk,
            const float* __restrict__ Wv)
{
    int bz = blockIdx.z;
    int b = bz / 3, p = bz - b * 3;
    const float* X = (p == 0 ? qin : cin) + b * CDIM * SEQ;
    const float* W = (p == 0 ? Wq : (p == 1 ? Wk : Wv));
    float* Y = (p == 0 ? g_q : (p == 1 ? g_k : g_v)) + b * CDIM * SEQ;

    __shared__ float As[16][132];
    __shared__ float Bs[16][132];

    int tid = threadIdx.x;
    int o0 = blockIdx.y * 128, n0 = blockIdx.x * 128;
    int ty = tid >> 4, tx = tid & 15;

    float2 acc2[8][4];
#pragma unroll
    for (int i = 0; i < 8; i++)
#pragma unroll
        for (int j = 0; j < 4; j++) acc2[i][j] = make_float2(0.f, 0.f);

    int arow = tid >> 2, acol = (tid & 3) << 2;
    int brow = tid >> 5, bcol = (tid & 31) << 2;

    for (int k0 = 0; k0 < CDIM; k0 += 16) {
#pragma unroll
        for (int r = 0; r < 2; r++) {
            float4 w4 = *(const float4*)&W[(o0 + arow + r * 64) * CDIM + k0 + acol];
            As[acol + 0][arow + r * 64] = w4.x;
            As[acol + 1][arow + r * 64] = w4.y;
            As[acol + 2][arow + r * 64] = w4.z;
            As[acol + 3][arow + r * 64] = w4.w;
        }
#pragma unroll
        for (int r = 0; r < 2; r++) {
            *(float4*)&Bs[brow + r * 8][bcol] =
                *(const float4*)&X[(k0 + brow + r * 8) * SEQ + n0 + bcol];
        }
        __syncthreads();
#pragma unroll
        for (int kk = 0; kk < 16; kk++) {
            float a[8];
            *(float4*)(a)     = *(float4*)&As[kk][ty * 8];
            *(float4*)(a + 4) = *(float4*)&As[kk][ty * 8 + 4];
            float4 b01 = *(float4*)&Bs[kk][tx * 8];
            float4 b23 = *(float4*)&Bs[kk][tx * 8 + 4];
            float2 bp[4] = { make_float2(b01.x, b01.y), make_float2(b01.z, b01.w),
                             make_float2(b23.x, b23.y), make_float2(b23.z, b23.w) };
#pragma unroll
            for (int i = 0; i < 8; i++) {
                float2 a2 = make_float2(a[i], a[i]);
#pragma unroll
                for (int pp = 0; pp < 4; pp++)
                    acc2[i][pp] = ffma2(a2, bp[pp], acc2[i][pp]);
            }
        }
        __syncthreads();
    }
#pragma unroll
    for (int i = 0; i < 8; i++) {
        int o = o0 + ty * 8 + i;
        float4 w0 = make_float4(acc2[i][0].x, acc2[i][0].y, acc2[i][1].x, acc2[i][1].y);
        float4 w1 = make_float4(acc2[i][2].x, acc2[i][2].y, acc2[i][3].x, acc2[i][3].y);
        *(float4*)&Y[o * SEQ + n0 + tx * 8]     = w0;
        *(float4*)&Y[o * SEQ + n0 + tx * 8 + 4] = w1;
    }
}

// ---------------- logits ----------------
__global__ void __launch_bounds__(256)
attn_kernel()
{
    int bh = blockIdx.z;
    int b = bh / NH, h = bh - b * NH;
    const float* Q  = g_q + (b * CDIM + h * DH) * SEQ;
    const float* Kp = g_k + (b * CDIM + h * DH) * SEQ;
    float* Ao = g_attn + (size_t)bh * SEQ * SEQ;

    __shared__ float Qs[16][132];
    __shared__ float Ks[16][132];

    int tid = threadIdx.x;
    int n0 = blockIdx.y * 128, m0 = blockIdx.x * 128;
    int ty = tid >> 4, tx = tid & 15;

    float2 acc2[8][4];
#pragma unroll
    for (int i = 0; i < 8; i++)
#pragma unroll
        for (int j = 0; j < 4; j++) acc2[i][j] = make_float2(0.f, 0.f);

    int brow = tid >> 5, bcol = (tid & 31) << 2;

    for (int k0 = 0; k0 < DH; k0 += 16) {
#pragma unroll
        for (int r = 0; r < 2; r++) {
            *(float4*)&Qs[brow + r * 8][bcol] =
                *(const float4*)&Q[(k0 + brow + r * 8) * SEQ + n0 + bcol];
            *(float4*)&Ks[brow + r * 8][bcol] =
                *(const float4*)&Kp[(k0 + brow + r * 8) * SEQ + m0 + bcol];
        }
        __syncthreads();
#pragma unroll
        for (int kk = 0; kk < 16; kk++) {
            float a[8];
            *(float4*)(a)     = *(float4*)&Qs[kk][ty * 8];
            *(float4*)(a + 4) = *(float4*)&Qs[kk][ty * 8 + 4];
            float4 b01 = *(float4*)&Ks[kk][tx * 8];
            float4 b23 = *(float4*)&Ks[kk][tx * 8 + 4];
            float2 bp[4] = { make_float2(b01.x, b01.y), make_float2(b01.z, b01.w),
                             make_float2(b23.x, b23.y), make_float2(b23.z, b23.w) };
#pragma unroll
            for (int i = 0; i < 8; i++) {
                float2 a2 = make_float2(a[i], a[i]);
#pragma unroll
                for (int pp = 0; pp < 4; pp++)
                    acc2[i][pp] = ffma2(a2, bp[pp], acc2[i][pp]);
            }
        }
        __syncthreads();
    }
#pragma unroll
    for (int i = 0; i < 8; i++) {
        int n = n0 + ty * 8 + i;
        float4 w0 = make_float4(acc2[i][0].x * SCALEF, acc2[i][0].y * SCALEF,
                                acc2[i][1].x * SCALEF, acc2[i][1].y * SCALEF);
        float4 w1 = make_float4(acc2[i][2].x * SCALEF, acc2[i][2].y * SCALEF,
                                acc2[i][3].x * SCALEF, acc2[i][3].y * SCALEF);
        *(float4*)&Ao[(size_t)n * SEQ + m0 + tx * 8]     = w0;
        *(float4*)&Ao[(size_t)n * SEQ + m0 + tx * 8 + 4] = w1;
    }
}

// ---------------- softmax fused with 12-bit histogram ----------------
__global__ void __launch_bounds__(256)
softhist_kernel()
{
    int map = blockIdx.y;
    __shared__ unsigned hist[4096];
    int tid = threadIdx.x;
    for (int i = tid; i < 4096; i += 256) hist[i] = 0u;
    __syncthreads();

    int warp = tid >> 5, lane = tid & 31;
    float* base = g_attn + ((size_t)map << 20);

    for (int rr = 0; rr < 4; rr++) {
        int row = blockIdx.x * 32 + warp * 4 + rr;
        float* A = base + (size_t)row * SEQ;
        float4 v[8];
        float mx = -3.4e38f;
#pragma unroll
        for (int j = 0; j < 8; j++) {
            v[j] = *(float4*)&A[j * 128 + lane * 4];
            mx = fmaxf(mx, fmaxf(fmaxf(v[j].x, v[j].y), fmaxf(v[j].z, v[j].w)));
        }
#pragma unroll
        for (int o = 16; o; o >>= 1) mx = fmaxf(mx, __shfl_xor_sync(0xffffffffu, mx, o));
        float s = 0.f;
#pragma unroll
        for (int j = 0; j < 8; j++) {
            v[j].x = expf(v[j].x - mx); v[j].y = expf(v[j].y - mx);
            v[j].z = expf(v[j].z - mx); v[j].w = expf(v[j].w - mx);
            s += (v[j].x + v[j].y) + (v[j].z + v[j].w);
        }
#pragma unroll
        for (int o = 16; o; o >>= 1) s += __shfl_xor_sync(0xffffffffu, s, o);
#pragma unroll
        for (int j = 0; j < 8; j++) {
            float4 o4;
            o4.x = v[j].x / s; o4.y = v[j].y / s;
            o4.z = v[j].z / s; o4.w = v[j].w / s;
            *(float4*)&A[j * 128 + lane * 4] = o4;
            atomicAdd(&hist[__float_as_uint(o4.x) >> 20], 1u);
            atomicAdd(&hist[__float_as_uint(o4.y) >> 20], 1u);
            atomicAdd(&hist[__float_as_uint(o4.z) >> 20], 1u);
            atomicAdd(&hist[__float_as_uint(o4.w) >> 20], 1u);
        }
    }
    __syncthreads();
    for (int i = tid; i < 4096; i += 256) {
        unsigned c = hist[i];
        if (c) atomicAdd(&g_hA[map * 4096 + i], c);
    }
}

// ---------------- select digit 1 ----------------
__global__ void select1_kernel()
{
    int map = blockIdx.x, tid = threadIdx.x;
    __shared__ unsigned psum[256], ssum[256];
    __shared__ unsigned rD, rA;
    const unsigned* h = g_hA + map * 4096;
    unsigned s = 0;
    int b0 = tid * 16;
    for (int i = 0; i < 16; i++) s += h[b0 + i];
    psum[tid] = s;
    __syncthreads();
    if (tid == 0) {
        unsigned run = 0;
        for (int t = 255; t >= 0; t--) { ssum[t] = run; run += psum[t]; }
    }
    __syncthreads();
    unsigned target = KTOP;
    if (ssum[tid] < target && ssum[tid] + psum[tid] >= target) {
        unsigned acc = ssum[tid];
        for (int i = 15; i >= 0; i--) {
            unsigned c = h[b0 + i];
            if (acc + c >= target) { rD = (unsigned)(b0 + i); rA = acc; break; }
            acc += c;
        }
    }
    __syncthreads();
    if (tid == 0) { g_D1[map] = rD; g_t2[map] = target - rA; }
}

// ---------------- scan 2 ----------------
__global__ void __launch_bounds__(256)
scan2_kernel()
{
    int map = blockIdx.y, tid = threadIdx.x;
    unsigned D1 = g_D1[map];
    __shared__ unsigned hist[1024];
    for (int i = tid; i < 1024; i += 256) hist[i] = 0u;
    __syncthreads();

    const float* A = g_attn + ((size_t)map << 20);
    int fbase = blockIdx.x * 4096;
#pragma unroll 4
    for (int i = 0; i < 16; i++) {
        const float4 v = *(const float4*)&A[(size_t)(fbase + i * 256 + tid) * 4];
        unsigned k0 = __float_as_uint(v.x), k1 = __float_as_uint(v.y);
        unsigned k2 = __float_as_uint(v.z), k3 = __float_as_uint(v.w);
        if ((k0 >> 20) == D1) atomicAdd(&hist[(k0 >> 10) & 1023], 1u);
        if ((k1 >> 20) == D1) atomicAdd(&hist[(k1 >> 10) & 1023], 1u);
        if ((k2 >> 20) == D1) atomicAdd(&hist[(k2 >> 10) & 1023], 1u);
        if ((k3 >> 20) == D1) atomicAdd(&hist[(k3 >> 10) & 1023], 1u);
    }
    __syncthreads();
    for (int i = tid; i < 1024; i += 256) {
        unsigned c = hist[i];
        if (c) atomicAdd(&g_hB[map * 1024 + i], c);
    }
}

// ---------------- select digit 2 ----------------
__global__ void select2_kernel()
{
    int map = blockIdx.x, tid = threadIdx.x;   // 1024 threads
    __shared__ unsigned hist[1024];
    hist[tid] = g_hB[map * 1024 + tid];
    __syncthreads();
    if (tid == 0) {
        unsigned target = g_t2[map];
        unsigned acc = 0;
        for (int i = 1023; i >= 0; i--) {
            unsigned c = hist[i];
            if (acc + c >= target) { g_D2[map] = (unsigned)i; g_t3[map] = target - acc; break; }
            acc += c;
        }
    }
}

// ---------------- scan 3 ----------------
__global__ void __launch_bounds__(256)
scan3_kernel()
{
    int map = blockIdx.y, tid = threadIdx.x;
    unsigned key22 = (g_D1[map] << 10) | g_D2[map];
    __shared__ unsigned hist[1024];
    for (int i = tid; i < 1024; i += 256) hist[i] = 0u;
    __syncthreads();

    const float* A = g_attn + ((size_t)map << 20);
    int fbase = blockIdx.x * 4096;
#pragma unroll 4
    for (int i = 0; i < 16; i++) {
        const float4 v = *(const float4*)&A[(size_t)(fbase + i * 256 + tid) * 4];
        unsigned k0 = __float_as_uint(v.x), k1 = __float_as_uint(v.y);
        unsigned k2 = __float_as_uint(v.z), k3 = __float_as_uint(v.w);
        if ((k0 >> 10) == key22) atomicAdd(&hist[k0 & 1023], 1u);
        if ((k1 >> 10) == key22) atomicAdd(&hist[k1 & 1023], 1u);
        if ((k2 >> 10) == key22) atomicAdd(&hist[k2 & 1023], 1u);
        if ((k3 >> 10) == key22) atomicAdd(&hist[k3 & 1023], 1u);
    }
    __syncthreads();
    for (int i = tid; i < 1024; i += 256) {
        unsigned c = hist[i];
        if (c) atomicAdd(&g_hC[map * 1024 + i], c);
    }
}

// ---------------- select digit 3 (small) ----------------
__global__ void select3_kernel()
{
    int map = blockIdx.x, tid = threadIdx.x;   // 1024 threads
    __shared__ unsigned hist[1024];
    hist[tid] = g_hC[map * 1024 + tid];
    __syncthreads();
    if (tid == 0) {
        unsigned target = g_t3[map];
        unsigned acc = 0, D3 = 0, above = 0;
        for (int i = 1023; i >= 0; i--) {
            unsigned c = hist[i];
            if (acc + c >= target) { D3 = (unsigned)i; above = acc; break; }
            acc += c;
        }
        unsigned thr = (g_D1[map] << 20) | (g_D2[map] << 10) | D3;
        int need = (int)(target - above);
        int ceq = (int)hist[D3];
        g_thr[map] = thr;
        if (need >= ceq) { g_cut[map] = 0x7FFFFFFF; g_need[map] = -1; }
        else g_need[map] = need;
    }
}

// ---------------- grid-wide collect of threshold-equal indices ----------------
__global__ void __launch_bounds__(256)
eqcollect_kernel()
{
    int map = blockIdx.y, tid = threadIdx.x;
    if (g_need[map] < 0) return;
    unsigned thr = g_thr[map];
    const float* A = g_attn + ((size_t)map << 20);
    int fbase = blockIdx.x * 4096;
#pragma unroll 4
    for (int i = 0; i < 16; i++) {
        int fi = fbase + i * 256 + tid;
        const float4 v = *(const float4*)&A[(size_t)fi * 4];
        unsigned k[4] = { __float_as_uint(v.x), __float_as_uint(v.y),
                          __float_as_uint(v.z), __float_as_uint(v.w) };
#pragma unroll
        for (int q = 0; q < 4; q++) {
            if (k[q] == thr) {
                unsigned p = atomicAdd(&g_eqcnt[map], 1u);
                if (p < 4096u) g_eq[map * 4096 + p] = fi * 4 + q;
            }
        }
    }
}

// ---------------- resolve tie cut (lowest indices win) ----------------
__global__ void __launch_bounds__(1024)
cut_kernel()
{
    int map = blockIdx.x, tid = threadIdx.x;
    int need = g_need[map];
    if (need < 0) return;
    __shared__ int eqlist[4096];
    __shared__ int scut;
    int c = min((int)g_eqcnt[map], 4096);
    for (int i = tid; i < c; i += 1024) eqlist[i] = g_eq[map * 4096 + i];
    __syncthreads();
    for (int i = tid; i < c; i += 1024) {
        int x = eqlist[i];
        int r = 0;
        for (int j = 0; j < c; j++) r += (eqlist[j] <= x);
        if (r == need) scut = x;
    }
    __syncthreads();
    if (tid == 0) g_cut[map] = scut;
}

// ---------------- mask outputs + column sums (fused) ----------------
__global__ void __launch_bounds__(256)
maskout_colsum_kernel(float* __restrict__ out)
{
    int map = blockIdx.y, tid = threadIdx.x;
    unsigned thr = g_thr[map];
    int cut = g_cut[map];
    const float* A = g_attn + ((size_t)map << 20);
    int col = tid * 4;
    float4 sum = make_float4(0.f, 0.f, 0.f, 0.f);
    for (int r = 0; r < 16; r++) {
        int row = blockIdx.x * 16 + r;
        int im = row * SEQ + col;
        size_t e = ((size_t)map << 20) + (size_t)im;
        float4 a = *(const float4*)&A[im];
        unsigned b0 = __float_as_uint(a.x), b1 = __float_as_uint(a.y);
        unsigned b2 = __float_as_uint(a.z), b3 = __float_as_uint(a.w);
        bool s0 = (b0 > thr) || (b0 == thr && (im + 0) <= cut);
        bool s1 = (b1 > thr) || (b1 == thr && (im + 1) <= cut);
        bool s2 = (b2 > thr) || (b2 == thr && (im + 2) <= cut);
        bool s3 = (b3 > thr) || (b3 == thr && (im + 3) <= cut);
        float4 msk = make_float4(s0 ? 1.f : 0.f, s1 ? 1.f : 0.f, s2 ? 1.f : 0.f, s3 ? 1.f : 0.f);
        float4 ac  = make_float4(s0 ? a.x : 0.f, s1 ? a.y : 0.f, s2 ? a.z : 0.f, s3 ? a.w : 0.f);
        float4 an  = make_float4(s0 ? 0.f : a.x, s1 ? 0.f : a.y, s2 ? 0.f : a.z, s3 ? 0.f : a.w);
        stcs4(&out[AC_OFF + e], ac);
        stcs4(&out[AN_OFF + e], an);
        stcs4(&out[BM_OFF + e], msk);
        sum.x += a.x; sum.y += a.y; sum.z += a.z; sum.w += a.w;
    }
    *(float4*)&g_part[((map * 64 + blockIdx.x) << 10) + col] = sum;
}

__global__ void mapfinal_kernel(float* __restrict__ out)
{
    int b = blockIdx.x, tid = threadIdx.x;
    float4 acc = make_float4(0.f, 0.f, 0.f, 0.f);
    for (int j = 0; j < 384; j++) {
        float4 v = *(const float4*)&g_part[((b * 384 + j) << 10) + tid * 4];
        acc.x += v.x; acc.y += v.y; acc.z += v.z; acc.w += v.w;
    }
    const float s = 1.f / 6144.f;
    *(float4*)&out[AM_OFF + b * SEQ + tid * 4] =
        make_float4(acc.x * s, acc.y * s, acc.z * s, acc.w * s);
}

// ---------------- attn @ V ----------------
__global__ void __launch_bounds__(256)
av_kernel()
{
    int bh = blockIdx.z;
    int b = bh / NH, h = bh - b * NH;
    const float* A = g_attn + ((size_t)bh << 20);
    const float* V = g_v + (b * CDIM + h * DH) * SEQ;
    float* O = g_o + (b * CDIM + h * DH) * SEQ;
    int n0 = blockIdx.x * 128;
    int tid = threadIdx.x;

    __shared__ float Vs[32][68];
    __shared__ float Ans[32][130];

    int ty = tid >> 4, tx = tid & 15;
    float2 acc2[4][4];
#pragma unroll
    for (int i = 0; i < 4; i++)
#pragma unroll
        for (int j = 0; j < 4; j++) acc2[i][j] = make_float2(0.f, 0.f);

    int lrow = tid >> 3, lcol = (tid & 7) << 2;

    for (int m0 = 0; m0 < SEQ; m0 += 32) {
#pragma unroll
        for (int p = 0; p < 2; p++) {
            int d = lrow + p * 32;
            float4 t = *(const float4*)&V[(size_t)d * SEQ + m0 + lcol];
            Vs[lcol + 0][d] = t.x; Vs[lcol + 1][d] = t.y;
            Vs[lcol + 2][d] = t.z; Vs[lcol + 3][d] = t.w;
        }
#pragma unroll
        for (int p = 0; p < 4; p++) {
            int n = lrow + p * 32;
            float4 t = *(const float4*)&A[(size_t)(n0 + n) * SEQ + m0 + lcol];
            Ans[lcol + 0][n] = t.x; Ans[lcol + 1][n] = t.y;
            Ans[lcol + 2][n] = t.z; Ans[lcol + 3][n] = t.w;
        }
        __syncthreads();
#pragma unroll
        for (int kk = 0; kk < 32; kk++) {
            float a[4];
            *(float4*)(a) = *(float4*)&Vs[kk][ty * 4];
            float2 bp[4];
#pragma unroll
            for (int p = 0; p < 4; p++) bp[p] = *(float2*)&Ans[kk][tx * 8 + 2 * p];
#pragma unroll
            for (int i = 0; i < 4; i++) {
                float2 a2 = make_float2(a[i], a[i]);
#pragma unroll
                for (int p = 0; p < 4; p++)
                    acc2[i][p] = ffma2(a2, bp[p], acc2[i][p]);
            }
        }
        __syncthreads();
    }
#pragma unroll
    for (int i = 0; i < 4; i++) {
        int d = ty * 4 + i;
        float4 w0 = make_float4(acc2[i][0].x, acc2[i][0].y, acc2[i][1].x, acc2[i][1].y);
        float4 w1 = make_float4(acc2[i][2].x, acc2[i][2].y, acc2[i][3].x, acc2[i][3].y);
        *(float4*)&O[(size_t)d * SEQ + n0 + tx * 8]     = w0;
        *(float4*)&O[(size_t)d * SEQ + n0 + tx * 8 + 4] = w1;
    }
}

// ---------------- output projection ----------------
__global__ void __launch_bounds__(256)
oproj_kernel(const float* __restrict__ Wo, const float* __restrict__ bo,
             float* __restrict__ out)
{
    int b = blockIdx.z;
    const float* X = g_o + b * CDIM * SEQ;

    __shared__ float As[16][132];
    __shared__ float Bs[16][132];

    int tid = threadIdx.x;
    int o0 = blockIdx.y * 128, n0 = blockIdx.x * 128;
    int ty = tid >> 4, tx = tid & 15;

    float2 acc2[8][4];
#pragma unroll
    for (int i = 0; i < 8; i++)
#pragma unroll
        for (int j = 0; j < 4; j++) acc2[i][j] = make_float2(0.f, 0.f);

    int arow = tid >> 2, acol = (tid & 3) << 2;
    int brow = tid >> 5, bcol = (tid & 31) << 2;

    for (int k0 = 0; k0 < CDIM; k0 += 16) {
#pragma unroll
        for (int r = 0; r < 2; r++) {
            float4 w4 = *(const float4*)&Wo[(o0 + arow + r * 64) * CDIM + k0 + acol];
            As[acol + 0][arow + r * 64] = w4.x;
            As[acol + 1][arow + r * 64] = w4.y;
            As[acol + 2][arow + r * 64] = w4.z;
            As[acol + 3][arow + r * 64] = w4.w;
        }
#pragma unroll
        for (int r = 0; r < 2; r++) {
            *(float4*)&Bs[brow + r * 8][bcol] =
                *(const float4*)&X[(k0 + brow + r * 8) * SEQ + n0 + bcol];
        }
        __syncthreads();
#pragma unroll
        for (int kk = 0; kk < 16; kk++) {
            float a[8];
            *(float4*)(a)     = *(float4*)&As[kk][ty * 8];
            *(float4*)(a + 4) = *(float4*)&As[kk][ty * 8 + 4];
            float4 b01 = *(float4*)&Bs[kk][tx * 8];
            float4 b23 = *(float4*)&Bs[kk][tx * 8 + 4];
            float2 bp[4] = { make_float2(b01.x, b01.y), make_float2(b01.z, b01.w),
                             make_float2(b23.x, b23.y), make_float2(b23.z, b23.w) };
#pragma unroll
            for (int i = 0; i < 8; i++) {
                float2 a2 = make_float2(a[i], a[i]);
#pragma unroll
                for (int pp = 0; pp < 4; pp++)
                    acc2[i][pp] = ffma2(a2, bp[pp], acc2[i][pp]);
            }
        }
        __syncthreads();
    }
#pragma unroll
    for (int i = 0; i < 8; i++) {
        int o = o0 + ty * 8 + i;
        float bias = __ldg(&bo[o]);
        float4 w0 = make_float4(acc2[i][0].x + bias, acc2[i][0].y + bias,
                                acc2[i][1].x + bias, acc2[i][1].y + bias);
        float4 w1 = make_float4(acc2[i][2].x + bias, acc2[i][2].y + bias,
                                acc2[i][3].x + bias, acc2[i][3].y + bias);
        stcs4(&out[OP_OFF + (size_t)(b * CDIM + o) * SEQ + n0 + tx * 8], w0);
        stcs4(&out[OP_OFF + (size_t)(b * CDIM + o) * SEQ + n0 + tx * 8 + 4], w1);
    }
}

// ---------------- launch ----------------
extern "C" void kernel_launch(void* const* d_in, const int* in_sizes, int n_in,
                              void* d_out, int out_size)
{
    (void)in_sizes; (void)n_in; (void)out_size;
    const float* query   = (const float*)d_in[0];
    const float* context = (const float*)d_in[1];
    const float* Wq = (const float*)d_in[2];
    const float* Wk = (const float*)d_in[3];
    const float* Wv = (const float*)d_in[4];
    const float* Wo = (const float*)d_in[5];
    const float* bo = (const float*)d_in[6];
    float* out = (float*)d_out;

    zero_kernel<<<145, 1024>>>();
    proj_kernel<<<dim3(8, 3, 12), 256>>>(query, context, Wq, Wk, Wv);
    attn_kernel<<<dim3(8, 8, 24), 256>>>();
    softhist_kernel<<<dim3(32, 24), 256>>>();
    select1_kernel<<<24, 256>>>();
    scan2_kernel<<<dim3(64, 24), 256>>>();
    select2_kernel<<<24, 1024>>>();
    scan3_kernel<<<dim3(64, 24), 256>>>();
    select3_kernel<<<24, 1024>>>();
    eqcollect_kernel<<<dim3(64, 24), 256>>>();
    cut_kernel<<<24, 1024>>>();
    maskout_colsum_kernel<<<dim3(64, 24), 256>>>(out);
    mapfinal_kernel<<<4, 256>>>(out);
    av_kernel<<<dim3(8, 1, 24), 256>>>();
    oproj_kernel<<<dim3(8, 3, 4), 256>>>(Wo, bo, out);
}